// round 13
// baseline (speedup 1.0000x reference)
#include <cuda_runtime.h>
#include <cuda_bf16.h>
#include <cuda_fp16.h>
#include <math.h>
#include <float.h>
#include <stdint.h>

#define S 2048
#define D 4096
#define H 32
#define HD 128
#define KH 128
#define KD 64
#define HEAVY 256
#define RECENT 256
#define NSEL (S - RECENT)   // 1792

typedef __nv_bfloat16 bf16;
typedef __half fp16;

// ---------------- scratch (device globals; zero-initialized at load) ----------------
__device__ float g_q[(size_t)S * D];
__device__ float g_k[(size_t)S * D];
__device__ float g_v[(size_t)S * D];
__device__ __align__(16) bf16 g_hsh[(size_t)S * D];
__device__ __align__(16) bf16 g_hsl[(size_t)S * D];
__device__ __align__(16) fp16 g_hs16[(size_t)S * D];
__device__ __align__(16) bf16 g_qh[(size_t)S * D];
__device__ __align__(16) bf16 g_ql[(size_t)S * D];
__device__ __align__(16) bf16 g_kh[(size_t)S * D];
__device__ __align__(16) bf16 g_kl[(size_t)S * D];
__device__ __align__(16) fp16 g_q16[(size_t)S * D];
__device__ __align__(16) fp16 g_k16[(size_t)S * D];
__device__ __align__(16) fp16 g_vt16[(size_t)H * HD * S];
__device__ __align__(16) bf16 g_wqth[(size_t)D * D];
__device__ __align__(16) bf16 g_wqtl[(size_t)D * D];
__device__ __align__(16) bf16 g_wkth[(size_t)D * D];
__device__ __align__(16) bf16 g_wktl[(size_t)D * D];
__device__ __align__(16) fp16 g_wvt16[(size_t)D * D];
__device__ __align__(16) fp16 g_wot16[(size_t)D * D];
__device__ __align__(16) fp16 g_kq1t[(size_t)H * KH * HD];
__device__ __align__(16) fp16 g_kk1t[(size_t)H * KH * HD];
__device__ __align__(16) fp16 g_kq2t[(size_t)H * KD * KH];
__device__ __align__(16) fp16 g_kk2t[(size_t)H * KD * KH];
__device__ __align__(16) fp16 g_t116[(size_t)H * S * KH];
__device__ float g_kkA[(size_t)H * S * KD];
__device__ float g_kker[(size_t)H * S * KD];
__device__ float g_logits[(size_t)H * S * S];   // 512 MB
__device__ __align__(16) fp16 g_ph[(size_t)H * S * S];        // 256 MB
__device__ __align__(16) fp16 g_ctx16[(size_t)S * D];
__device__ float g_hpart[(size_t)H * 8 * KD * HD];
__device__ float g_zpart[(size_t)H * 8 * KD];
__device__ float g_scores[H * S];
__device__ float g_elim[H * S];

__device__ __forceinline__ float gelu_f(float x) {
    return 0.5f * x * (1.0f + erff(x * 0.7071067811865476f));
}

// FMA-pipe exp: exp(x) = 2^n * exp(f*ln2), |f| <= 0.5, degree-5 Taylor (rel err ~2.4e-6)
__device__ __forceinline__ float fast_exp(float x) {
    float y = x * 1.4426950408889634f;
    float n = rintf(y);
    float t = (y - n) * 0.6931471805599453f;
    float p = 8.3333333e-3f;
    p = fmaf(p, t, 4.1666667e-2f);
    p = fmaf(p, t, 1.6666667e-1f);
    p = fmaf(p, t, 0.5f);
    p = fmaf(p, t, 1.0f);
    p = fmaf(p, t, 1.0f);
    int e = (int)n;
    e = e < -126 ? -126 : (e > 126 ? 126 : e);
    return p * __int_as_float((e + 127) << 23);
}

// ============================ PTX helpers ============================
__device__ __forceinline__ uint32_t smem_u32(const void* p) {
    uint32_t a;
    asm("{ .reg .u64 t; cvta.to.shared.u64 t, %1; cvt.u32.u64 %0, t; }" : "=r"(a) : "l"(p));
    return a;
}
__device__ __forceinline__ void cp16(uint32_t dst, const void* src) {
    asm volatile("cp.async.cg.shared.global [%0], [%1], 16;" :: "r"(dst), "l"(src));
}
#define CP_COMMIT() asm volatile("cp.async.commit_group;" ::: "memory")
#define CP_WAIT(n)  asm volatile("cp.async.wait_group %0;" :: "n"(n) : "memory")

#define LDSM4(r, addr) \
    asm volatile("ldmatrix.sync.aligned.m8n8.x4.shared.b16 {%0,%1,%2,%3}, [%4];" \
        : "=r"((r)[0]), "=r"((r)[1]), "=r"((r)[2]), "=r"((r)[3]) : "r"(addr))

#define MMA_BF(d, a, b) \
    asm volatile("mma.sync.aligned.m16n8k16.row.col.f32.bf16.bf16.f32 " \
        "{%0,%1,%2,%3}, {%4,%5,%6,%7}, {%8,%9}, {%0,%1,%2,%3};" \
        : "+f"((d)[0]), "+f"((d)[1]), "+f"((d)[2]), "+f"((d)[3]) \
        : "r"((a)[0]), "r"((a)[1]), "r"((a)[2]), "r"((a)[3]), "r"((b)[0]), "r"((b)[1]))

#define MMA_FP(d, a, b) \
    asm volatile("mma.sync.aligned.m16n8k16.row.col.f32.f16.f16.f32 " \
        "{%0,%1,%2,%3}, {%4,%5,%6,%7}, {%8,%9}, {%0,%1,%2,%3};" \
        : "+f"((d)[0]), "+f"((d)[1]), "+f"((d)[2]), "+f"((d)[3]) \
        : "r"((a)[0]), "r"((a)[1]), "r"((a)[2]), "r"((a)[3]), "r"((b)[0]), "r"((b)[1]))

// ============================ HMMA multi-pass GEMM ============================
// C[m,n] = epi( scale * sum_k (A0 [+A1])[m,k] * (B0 [+B1])[n,k] )  (B N-major)
// passes: (a0,b0); +(a0,b1) if NB==2; +(a1,b0) if NA==2.   (lo*lo dropped)
// modes: 0 none, 1 gelu, 2 abs(gelu), 3 |aux[n]|*gelu
// causal: 0 none; 1 logits (skip n0>m0 tiles, zero n>m); 2 K limited to m0+128.
// NSTGv-stage cp.async pipeline, one __syncthreads per K-chunk; smem sized so
// every variant fits 2 CTAs/SM (the R11 3-stage config dropped to 1 CTA/SM).

template <int NT, int NA, int NB, bool BF, int BKEv, int NSTGv>
__global__ __launch_bounds__(256, 2)
void hm_gemm(const uint16_t* __restrict__ A0, const uint16_t* __restrict__ A1,
             const uint16_t* __restrict__ B0, const uint16_t* __restrict__ B1,
             float* __restrict__ Cf, fp16* __restrict__ C16,
             int K, int lda, int ldb, int ldc,
             long long sA, long long sB, long long sC,
             float scale, int mode, int causal,
             const float* __restrict__ aux, long long sAux)
{
    constexpr int PITCH = BKEv * 2 + 16;   // data bytes + 16 pad per smem row
    constexpr int CH = BKEv / 8;           // 16B chunks per row
    constexpr int WN = NT / 2;             // warp n-extent (4x2 warp grid)
    constexpr int NT8 = WN / 8;            // n8 tiles per warp
    constexpr int ASZ = 128 * PITCH;
    constexpr int BSZ = NT * PITCH;
    constexpr int STAGE = NA * ASZ + NB * BSZ;
    extern __shared__ char smem[];

    const int tid = threadIdx.x;
    const int lane = tid & 31, wrp = tid >> 5;
    const int wm = wrp >> 1, wn = wrp & 1;
    const int m0 = blockIdx.y * 128;
    const int n0 = blockIdx.x * NT;
    if (causal == 1 && n0 > m0) return;

    const long long z = blockIdx.z;
    const uint16_t* Aop[2] = { A0 + z * sA, A1 ? A1 + z * sA : nullptr };
    const uint16_t* Bop[2] = { B0 + z * sB, B1 ? B1 + z * sB : nullptr };
    if (Cf) Cf += z * sC;
    if (C16) C16 += z * sC;
    if (aux) aux += z * sAux;

    const uint32_t sbase = smem_u32(smem);

    float acc[2][NT8][4];
#pragma unroll
    for (int i = 0; i < 2; i++)
#pragma unroll
        for (int j = 0; j < NT8; j++)
#pragma unroll
            for (int t = 0; t < 4; t++) acc[i][j][t] = 0.f;

    const int Keff = (causal == 2) ? (m0 + 128) : K;
    const int nch = Keff / BKEv;

    auto load_stage = [&](int kc, int st) {
        const int k0 = kc * BKEv;
        const uint32_t base = sbase + st * STAGE;
        // A operands: NA * 128 rows * CH chunks
#pragma unroll
        for (int it = 0; it < NA * 128 * CH / 256; it++) {
            int idx = tid + it * 256;
            int a = idx / (128 * CH);
            int rem = idx % (128 * CH);
            int r = rem / CH, c = rem % CH;
            cp16(base + a * ASZ + r * PITCH + c * 16,
                 Aop[a] + (size_t)(m0 + r) * lda + k0 + c * 8);
        }
        // B operands: NB * NT rows * CH chunks
#pragma unroll
        for (int it = 0; it < NB * NT * CH / 256; it++) {
            int idx = tid + it * 256;
            int b = idx / (NT * CH);
            int rem = idx % (NT * CH);
            int r = rem / CH, c = rem % CH;
            cp16(base + NA * ASZ + b * BSZ + r * PITCH + c * 16,
                 Bop[b] + (size_t)(n0 + r) * ldb + k0 + c * 8);
        }
        CP_COMMIT();
    };

    auto compute_stage = [&](int st) {
        const uint32_t base = sbase + st * STAGE;
#pragma unroll
        for (int ks = 0; ks < BKEv / 16; ks++) {
            const uint32_t ksoff = ks * 32;           // bytes (16 elems)
            uint32_t af[2][4];                        // one A operand's frags
            uint32_t bfr[NT8][2];                     // one B operand's frags

            auto loadA = [&](int a) {
#pragma unroll
                for (int mt = 0; mt < 2; mt++) {
                    int row = wm * 32 + mt * 16 + (lane & 15);
                    uint32_t col = ksoff + ((lane & 16) ? 16 : 0);
                    LDSM4(af[mt], base + a * ASZ + row * PITCH + col);
                }
            };
            auto loadB = [&](int b) {
#pragma unroll
                for (int jp = 0; jp < NT8 / 2; jp++) {
                    int row = wn * WN + jp * 16 + (lane & 7) + ((lane & 16) >> 1);
                    uint32_t col = ksoff + ((lane & 8) ? 16 : 0);
                    uint32_t r4[4];
                    LDSM4(r4, base + NA * ASZ + b * BSZ + row * PITCH + col);
                    bfr[2 * jp][0] = r4[0]; bfr[2 * jp][1] = r4[1];
                    bfr[2 * jp + 1][0] = r4[2]; bfr[2 * jp + 1][1] = r4[3];
                }
            };
            auto domma = [&]() {
#pragma unroll
                for (int mt = 0; mt < 2; mt++)
#pragma unroll
                    for (int nt = 0; nt < NT8; nt++) {
                        if (BF) { MMA_BF(acc[mt][nt], af[mt], bfr[nt]); }
                        else    { MMA_FP(acc[mt][nt], af[mt], bfr[nt]); }
                    }
            };

            loadA(0); loadB(0); domma();          // a0*b0
            if (NB == 2) { loadB(1); domma(); }   // a0*b1
            if (NA == 2) {                        // a1*b0
                loadA(1);
                if (NB == 2) loadB(0);
                domma();
            }
        }
    };

    // ---- prologue: fill stages 0..NSTGv-2 ----
#pragma unroll
    for (int s = 0; s < NSTGv - 1; s++) {
        if (s < nch) load_stage(s, s); else CP_COMMIT();
    }
    CP_WAIT(NSTGv - 2);
    __syncthreads();

    // ---- mainloop: load(i+NSTGv-1); compute(i); wait; sync ----
    for (int i = 0; i < nch; i++) {
        if (i + NSTGv - 1 < nch) load_stage(i + NSTGv - 1, (i + NSTGv - 1) % NSTGv);
        else CP_COMMIT();
        compute_stage(i % NSTGv);
        CP_WAIT(NSTGv - 2);
        __syncthreads();
    }

    // ---- epilogue ----
    const int r = lane >> 2, c = (lane & 3) * 2;
#pragma unroll
    for (int mt = 0; mt < 2; mt++) {
#pragma unroll
        for (int nt = 0; nt < NT8; nt++) {
#pragma unroll
            for (int e = 0; e < 4; e++) {
                const int m = m0 + wm * 32 + mt * 16 + r + ((e >> 1) ? 8 : 0);
                const int n = n0 + wn * WN + nt * 8 + c + (e & 1);
                float v = acc[mt][nt][e] * scale;
                if (mode == 1)      v = gelu_f(v);
                else if (mode == 2) v = fabsf(gelu_f(v));
                else if (mode == 3) v = fabsf(aux[n]) * gelu_f(v);
                if (causal == 1 && n > m) v = 0.f;
                const size_t o = (size_t)m * ldc + n;
                if (Cf)  Cf[o] = v;
                if (C16) C16[o] = __float2half_rn(v);
            }
        }
    }
}

// ---------------- hs: fp32 -> bf16 hi/lo + fp16 ----------------
__global__ void split_hs_kernel(const float* __restrict__ x, bf16* __restrict__ hi,
                                bf16* __restrict__ lo, fp16* __restrict__ h16, int n)
{
    int i = blockIdx.x * blockDim.x + threadIdx.x;
    if (i >= n) return;
    float v = x[i];
    bf16 h = __float2bfloat16(v);
    hi[i] = h;
    lo[i] = __float2bfloat16(v - __bfloat162float(h));
    h16[i] = __float2half_rn(v);
}

// ---------------- split+transpose fp32 -> bf16 hi/lo (for wq, wk) ----------------
__global__ void splitT_kernel(const float* __restrict__ in, bf16* __restrict__ oh,
                              bf16* __restrict__ ol, int R, int ldin,
                              long long sIn, long long sOut)
{
    in += (long long)blockIdx.z * sIn;
    oh += (long long)blockIdx.z * sOut;
    ol += (long long)blockIdx.z * sOut;
    __shared__ float t[32][33];
    int r0 = blockIdx.y * 32, c0 = blockIdx.x * 32;
    int tx = threadIdx.x, ty = threadIdx.y;  // (32, 8)
#pragma unroll
    for (int i = 0; i < 4; i++)
        t[ty + 8 * i][tx] = in[(size_t)(r0 + ty + 8 * i) * ldin + c0 + tx];
    __syncthreads();
#pragma unroll
    for (int i = 0; i < 4; i++) {
        int oc = ty + 8 * i;
        float v = t[tx][oc];
        size_t o = (size_t)(c0 + oc) * R + r0 + tx;
        bf16 h = __float2bfloat16(v);
        oh[o] = h;
        ol[o] = __float2bfloat16(v - __bfloat162float(h));
    }
}

// ---------------- transpose fp32 -> fp16 single ----------------
__global__ void splitT16_kernel(const float* __restrict__ in, fp16* __restrict__ o16,
                                int R, int ldin, long long sIn, long long sOut)
{
    in += (long long)blockIdx.z * sIn;
    o16 += (long long)blockIdx.z * sOut;
    __shared__ float t[32][33];
    int r0 = blockIdx.y * 32, c0 = blockIdx.x * 32;
    int tx = threadIdx.x, ty = threadIdx.y;
#pragma unroll
    for (int i = 0; i < 4; i++)
        t[ty + 8 * i][tx] = in[(size_t)(r0 + ty + 8 * i) * ldin + c0 + tx];
    __syncthreads();
#pragma unroll
    for (int i = 0; i < 4; i++) {
        int oc = ty + 8 * i;
        o16[(size_t)(c0 + oc) * R + r0 + tx] = __float2half_rn(t[tx][oc]);
    }
}

// ---------------- rotary: fp32 q,k -> bf16 hi/lo + fp16 ----------------
__global__ void rotary_split_kernel(const float* __restrict__ q, const float* __restrict__ k,
                                    bf16* __restrict__ qh, bf16* __restrict__ ql,
                                    bf16* __restrict__ kh, bf16* __restrict__ kl,
                                    fp16* __restrict__ q16, fp16* __restrict__ k16)
{
    int idx = blockIdx.x * blockDim.x + threadIdx.x;
    if (idx >= S * H * 64) return;
    int i = idx & 63;
    int h = (idx >> 6) & 31;
    int s = idx >> 11;
    float inv = expf(-9.210340371976184f * (float)i / 64.0f);
    float ang = (float)s * inv;
    float sn, c;
    sincosf(ang, &sn, &c);
    long long base = (long long)s * D + h * HD;
    {
        float x1 = q[base + i], x2 = q[base + 64 + i];
        float r1 = x1 * c - x2 * sn;
        float r2 = x2 * c + x1 * sn;
        bf16 h1 = __float2bfloat16(r1); qh[base + i] = h1;      ql[base + i] = __float2bfloat16(r1 - __bfloat162float(h1));
        bf16 h2 = __float2bfloat16(r2); qh[base + 64 + i] = h2; ql[base + 64 + i] = __float2bfloat16(r2 - __bfloat162float(h2));
        q16[base + i] = __float2half_rn(r1);
        q16[base + 64 + i] = __float2half_rn(r2);
    }
    {
        float x1 = k[base + i], x2 = k[base + 64 + i];
        float r1 = x1 * c - x2 * sn;
        float r2 = x2 * c + x1 * sn;
        bf16 h1 = __float2bfloat16(r1); kh[base + i] = h1;      kl[base + i] = __float2bfloat16(r1 - __bfloat162float(h1));
        bf16 h2 = __float2bfloat16(r2); kh[base + 64 + i] = h2; kl[base + 64 + i] = __float2bfloat16(r2 - __bfloat162float(h2));
        k16[base + i] = __float2half_rn(r1);
        k16[base + 64 + i] = __float2half_rn(r2);
    }
}

// ---------------- k_ker interaction: kker = |kkA + (kkA @ ik) * scD2| ----------------
__global__ __launch_bounds__(256)
void interact_kernel(const float* __restrict__ kkA, const float* __restrict__ ik,
                     const float* __restrict__ sc2, float* __restrict__ kker)
{
    int h = blockIdx.y;
    int s0 = blockIdx.x * 64;
    int tid = threadIdx.x;
    __shared__ float sIK[KD][KD];
    __shared__ float sA[64][KD + 1];
    for (int idx = tid; idx < KD * KD; idx += 256)
        sIK[idx >> 6][idx & 63] = ik[(size_t)h * KD * KD + idx];
    for (int idx = tid; idx < 64 * KD; idx += 256) {
        int r = idx >> 6, e = idx & 63;
        sA[r][e] = kkA[((size_t)h * S + s0 + r) * KD + e];
    }
    __syncthreads();
    int r = tid >> 2;
    int f0 = (tid & 3) * 16;
#pragma unroll
    for (int ff = 0; ff < 16; ff++) {
        int f = f0 + ff;
        float sum = 0.f;
#pragma unroll
        for (int e = 0; e < KD; e++) sum += sA[r][e] * sIK[e][f];
        float val = sA[r][f] + sum * sc2[h * KD + f];
        kker[((size_t)h * S + s0 + r) * KD + f] = fabsf(val);
    }
}

// ---------------- fused causal softmax (no max shift, FMA exp): fp32 logits -> fp16 probs ----------------
__global__ void softmax_kernel(const float* __restrict__ logits, fp16* __restrict__ ph)
{
    int q = blockIdx.x;
    int h = blockIdx.y;
    const float* row = logits + ((size_t)h * S + q) * S;
    fp16* rh = ph + ((size_t)h * S + q) * S;
    int len = q + 1;
    int tid = threadIdx.x;
    __shared__ float red[128];

    float vals[16];
    float sum = 0.f;
#pragma unroll
    for (int i = 0; i < 16; i++) {
        int k = tid + i * 128;
        float e = 0.f;
        if (k < len) e = fast_exp(row[k]);
        vals[i] = e;
        sum += e;
    }
    red[tid] = sum; __syncthreads();
    for (int off = 64; off > 0; off >>= 1) {
        if (tid < off) red[tid] += red[tid + off];
        __syncthreads();
    }
    float inv = 1.0f / red[0];
#pragma unroll
    for (int i = 0; i < 16; i++) {
        int k = tid + i * 128;
        if (k < len) rh[k] = __float2half_rn(vals[i] * inv);
    }
}

// ---------------- column sums of probs (upper triangle is exactly 0) ----------------
__global__ void scores_kernel(const fp16* __restrict__ ph, float* __restrict__ scores)
{
    int h = blockIdx.y;
    int k = blockIdx.x * 256 + threadIdx.x;
    const fp16* p1 = ph + (size_t)h * S * S + k;
    float s = 0.f;
    for (int q = 0; q < S; q++)
        s += __half2float(p1[(size_t)q * S]);
    scores[h * S + k] = s;
}

// ---------------- top-HEAVY selection -> elim mask ----------------
__global__ __launch_bounds__(256)
void topk_kernel(const float* __restrict__ scores, float* __restrict__ elim)
{
    int h = blockIdx.x;
    int tid = threadIdx.x;
    __shared__ float sv[NSEL];
    __shared__ float rv[256];
    __shared__ int   ri[256];
    for (int j = tid; j < NSEL; j += 256) sv[j] = scores[h * S + j];
    for (int s = tid; s < S; s += 256) elim[h * S + s] = (s <= NSEL) ? 1.f : 0.f;
    __syncthreads();
    for (int iter = 0; iter < HEAVY; iter++) {
        float best = -1.f; int bi = 0x7fffffff;
        for (int j = tid; j < NSEL; j += 256) {
            float vv = sv[j];
            if (vv > best) { best = vv; bi = j; }
        }
        rv[tid] = best; ri[tid] = bi; __syncthreads();
        for (int off = 128; off > 0; off >>= 1) {
            if (tid < off) {
                float ov = rv[tid + off]; int oi = ri[tid + off];
                if (ov > rv[tid] || (ov == rv[tid] && oi < ri[tid])) { rv[tid] = ov; ri[tid] = oi; }
            }
            __syncthreads();
        }
        if (tid == 0) { int b = ri[0]; elim[h * S + b] = 0.f; sv[b] = -2.f; }
        __syncthreads();
    }
}

// ---------------- H_new / z_new partials over s-chunks ----------------
__global__ __launch_bounds__(256)
void hnew_part(const float* __restrict__ kker, const float* __restrict__ v,
               const float* __restrict__ elim,
               float* __restrict__ hp, float* __restrict__ zp)
{
    int h = blockIdx.x;
    int ch = blockIdx.y;   // 0..7, each 256 rows
    int tid = threadIdx.x;
    __shared__ float skk[32][KD];
    __shared__ float sv[32][HD];
    int dg = tid & 15;
    int eg = tid >> 4;
    float acc[4][8];
#pragma unroll
    for (int e = 0; e < 4; e++)
#pragma unroll
        for (int d = 0; d < 8; d++) acc[e][d] = 0.f;
    float zacc = 0.f;

    const float* kkh = kker + (size_t)h * S * KD;
    const float* vh  = v + h * HD;
    const int sBeg = ch * 256, sEnd = sBeg + 256;
    for (int s0 = sBeg; s0 < sEnd; s0 += 32) {
        for (int idx = tid; idx < 32 * KD; idx += 256) {
            int si = idx >> 6; int e = idx & 63;
            skk[si][e] = kkh[(size_t)(s0 + si) * KD + e] * elim[h * S + s0 + si];
        }
        for (int idx = tid; idx < 32 * HD; idx += 256) {
            int si = idx >> 7; int d = idx & 127;
            sv[si][d] = vh[(size_t)(s0 + si) * D + d];
        }
        __syncthreads();
        if (tid < KD) {
#pragma unroll
            for (int si = 0; si < 32; si++) zacc += skk[si][tid];
        }
#pragma unroll 4
        for (int si = 0; si < 32; si++) {
            float ke[4], vd[8];
#pragma unroll
            for (int e = 0; e < 4; e++) ke[e] = skk[si][eg * 4 + e];
#pragma unroll
            for (int d = 0; d < 8; d++) vd[d] = sv[si][dg * 8 + d];
#pragma unroll
            for (int e = 0; e < 4; e++)
#pragma unroll
                for (int d = 0; d < 8; d++)
                    acc[e][d] += ke[e] * vd[d];
        }
        __syncthreads();
    }
    float* hout = hp + ((size_t)h * 8 + ch) * KD * HD;
#pragma unroll
    for (int e = 0; e < 4; e++)
#pragma unroll
        for (int d = 0; d < 8; d++)
            hout[(eg * 4 + e) * HD + dg * 8 + d] = acc[e][d];
    if (tid < KD) zp[((size_t)h * 8 + ch) * KD + tid] = zacc;
}

__global__ void hnew_reduce(const float* __restrict__ hp, const float* __restrict__ zp,
                            float* __restrict__ Hout, float* __restrict__ zout)
{
    int i = blockIdx.x * 256 + threadIdx.x;   // over H*KD*HD
    if (i >= H * KD * HD) return;
    int h = i / (KD * HD);
    int r = i % (KD * HD);
    float s = 0.f;
#pragma unroll
    for (int c = 0; c < 8; c++) s += hp[((size_t)h * 8 + c) * KD * HD + r];
    Hout[i] = s;
    if (i < H * KD) {
        int hh = i / KD, e = i % KD;
        float z = 0.f;
#pragma unroll
        for (int c = 0; c < 8; c++) z += zp[((size_t)hh * 8 + c) * KD + e];
        zout[i] = z;
    }
}

// ---------------- host side ----------------
template <typename T>
static float* sym_f(T& sym) { void* p = nullptr; cudaGetSymbolAddress(&p, sym); return (float*)p; }
template <typename T>
static bf16* sym_b(T& sym) { void* p = nullptr; cudaGetSymbolAddress(&p, sym); return (bf16*)p; }
template <typename T>
static fp16* sym_h(T& sym) { void* p = nullptr; cudaGetSymbolAddress(&p, sym); return (fp16*)p; }

template <int NT, int NA, int NB, bool BF, int BKEv, int NSTGv>
static void launch_gemm(const void* A0, const void* A1, const void* B0, const void* B1,
                        float* Cf, fp16* C16,
                        int M, int N, int K, int lda, int ldb, int ldc,
                        long long sA, long long sB, long long sC, int batch,
                        float scale, int mode, int causal,
                        const float* aux = nullptr, long long sAux = 0)
{
    constexpr int PITCH = BKEv * 2 + 16;
    constexpr int STAGE = (NA * 128 + NB * NT) * PITCH;
    cudaFuncSetAttribute(hm_gemm<NT, NA, NB, BF, BKEv, NSTGv>,
                         cudaFuncAttributeMaxDynamicSharedMemorySize, NSTGv * STAGE);
    dim3 grid(N / NT, M / 128, batch);
    hm_gemm<NT, NA, NB, BF, BKEv, NSTGv><<<grid, 256, NSTGv * STAGE>>>(
        (const uint16_t*)A0, (const uint16_t*)A1, (const uint16_t*)B0, (const uint16_t*)B1,
        Cf, C16, K, lda, ldb, ldc, sA, sB, sC, scale, mode, causal, aux, sAux);
}

extern "C" void kernel_launch(void* const* d_in, const int* in_sizes, int n_in,
                              void* d_out, int out_size)
{
    const float* hs   = (const float*)d_in[0];
    const float* wq   = (const float*)d_in[1];
    const float* wk   = (const float*)d_in[2];
    const float* wv   = (const float*)d_in[3];
    const float* wo   = (const float*)d_in[4];
    const float* kq1  = (const float*)d_in[5];
    const float* kq2  = (const float*)d_in[6];
    const float* kk1  = (const float*)d_in[7];
    const float* kk2  = (const float*)d_in[8];
    const float* scD  = (const float*)d_in[9];
    const float* ik   = (const float*)d_in[10];
    const float* scD2 = (const float*)d_in[11];

    float* out   = (float*)d_out;
    float* outO  = out;
    float* outH  = out + (size_t)S * D;
    float* outZ  = outH + (size_t)H * KD * HD;
    float* outQk = outZ + (size_t)H * KD;

    float* q = sym_f(g_q);  float* k = sym_f(g_k);  float* v = sym_f(g_v);
    bf16 *hsh = sym_b(g_hsh), *hsl = sym_b(g_hsl);
    fp16 *hs16 = sym_h(g_hs16);
    bf16 *qh = sym_b(g_qh), *ql = sym_b(g_ql), *kh = sym_b(g_kh), *kl = sym_b(g_kl);
    fp16 *q16 = sym_h(g_q16), *k16 = sym_h(g_k16);
    fp16 *vt16 = sym_h(g_vt16);
    bf16 *wqth = sym_b(g_wqth), *wqtl = sym_b(g_wqtl);
    bf16 *wkth = sym_b(g_wkth), *wktl = sym_b(g_wktl);
    fp16 *wvt16 = sym_h(g_wvt16), *wot16 = sym_h(g_wot16);
    fp16 *kq1t = sym_h(g_kq1t), *kk1t = sym_h(g_kk1t);
    fp16 *kq2t = sym_h(g_kq2t), *kk2t = sym_h(g_kk2t);
    fp16 *t116 = sym_h(g_t116);
    fp16 *ph = sym_h(g_ph);
    fp16 *ctx16 = sym_h(g_ctx16);
    float* kkA = sym_f(g_kkA);
    float* kker = sym_f(g_kker);
    float* logits = sym_f(g_logits);
    float* hp = sym_f(g_hpart);
    float* zp = sym_f(g_zpart);
    float* scores = sym_f(g_scores);
    float* elim = sym_f(g_elim);

    // ---- 0) operand prep ----
    split_hs_kernel<<<(S * D + 255) / 256, 256>>>(hs, hsh, hsl, hs16, S * D);
    {
        dim3 g(D / 32, D / 32, 1), b(32, 8);
        splitT_kernel<<<g, b>>>(wq, wqth, wqtl, D, D, 0, 0);
        splitT_kernel<<<g, b>>>(wk, wkth, wktl, D, D, 0, 0);
        splitT16_kernel<<<g, b>>>(wv, wvt16, D, D, 0, 0);
        splitT16_kernel<<<g, b>>>(wo, wot16, D, D, 0, 0);
    }
    {
        dim3 g(KH / 32, HD / 32, H), b(32, 8);
        splitT16_kernel<<<g, b>>>(kq1, kq1t, HD, KH, (long long)HD * KH, (long long)KH * HD);
        splitT16_kernel<<<g, b>>>(kk1, kk1t, HD, KH, (long long)HD * KH, (long long)KH * HD);
    }
    {
        dim3 g(KD / 32, KH / 32, H), b(32, 8);
        splitT16_kernel<<<g, b>>>(kq2, kq2t, KH, KD, (long long)KH * KD, (long long)KD * KH);
        splitT16_kernel<<<g, b>>>(kk2, kk2t, KH, KD, (long long)KH * KD, (long long)KD * KH);
    }

    // ---- 1) QKV projections (3-pass: BKE=32 -> 80KB smem -> 2 CTAs/SM) ----
    launch_gemm<128, 2, 2, true, 32, 2>(hsh, hsl, wqth, wqtl, q, nullptr,
                                        S, D, D, D, D, D, 0, 0, 0, 1, 1.f, 0, 0);
    launch_gemm<128, 2, 2, true, 32, 2>(hsh, hsl, wkth, wktl, k, nullptr,
                                        S, D, D, D, D, D, 0, 0, 0, 1, 1.f, 0, 0);
    launch_gemm<128, 1, 1, false, 64, 2>(hs16, nullptr, wvt16, nullptr, v, nullptr,
                                         S, D, D, D, D, D, 0, 0, 0, 1, 1.f, 0, 0);

    // ---- 2) rotary ----
    rotary_split_kernel<<<(S * H * 64 + 255) / 256, 256>>>(q, k, qh, ql, kh, kl, q16, k16);

    // ---- 3) v^T fp16 per head ----
    {
        dim3 g(HD / 32, S / 32, H), b(32, 8);
        splitT16_kernel<<<g, b>>>(v, vt16, S, D, (long long)HD, (long long)HD * S);
    }

    // ---- 4) q_ker path (fp16 single) ----
    launch_gemm<128, 1, 1, false, 64, 2>(q16, nullptr, kq1t, nullptr, nullptr, t116,
                                         S, KH, HD, D, HD, KH,
                                         HD, (long long)KH * HD, (long long)S * KH, H, 1.f, 1, 0);
    launch_gemm<64, 1, 1, false, 64, 2>(t116, nullptr, kq2t, nullptr, outQk, nullptr,
                                        S, KD, KH, KH, KH, KD,
                                        (long long)S * KH, (long long)KD * KH, (long long)S * KD, H, 1.f, 2, 0);

    // ---- 5) k_ker path (fp16 single) ----
    launch_gemm<128, 1, 1, false, 64, 2>(k16, nullptr, kk1t, nullptr, nullptr, t116,
                                         S, KH, HD, D, HD, KH,
                                         HD, (long long)KH * HD, (long long)S * KH, H, 1.f, 1, 0);
    launch_gemm<64, 1, 1, false, 64, 2>(t116, nullptr, kk2t, nullptr, kkA, nullptr,
                                        S, KD, KH, KH, KH, KD,
                                        (long long)S * KH, (long long)KD * KH, (long long)S * KD, H, 1.f, 3, 0, scD, KD);

    // ---- 6) interaction -> kker ----
    {
        dim3 grid(S / 64, H);
        interact_kernel<<<grid, 256>>>(kkA, ik, scD2, kker);
    }

    // ---- 7) causal logits (bf16 3-pass: precision for top-k path) ----
    launch_gemm<128, 2, 2, true, 32, 2>(qh, ql, kh, kl, logits, nullptr,
                                        S, S, HD, D, D, S,
                                        HD, HD, (long long)S * S, H, 0.08838834764831843f, 0, 1);

    // ---- 8) fused softmax -> fp16 probs (FMA exp, no max shift) ----
    {
        dim3 grid(S, H);
        softmax_kernel<<<grid, 128>>>(logits, ph);
    }

    // ---- 9) scores / topk / hnew ----
    {
        dim3 grid(S / 256, H);
        scores_kernel<<<grid, 256>>>(ph, scores);
    }
    topk_kernel<<<H, 256>>>(scores, elim);
    {
        dim3 grid(H, 8);
        hnew_part<<<grid, 256>>>(kker, v, elim, hp, zp);
    }
    hnew_reduce<<<(H * KD * HD + 255) / 256, 256>>>(hp, zp, outH, outZ);

    // ---- 10) ctx = ph @ v16  (1-pass, causal K-limit) ----
    launch_gemm<128, 1, 1, false, 64, 2>(ph, nullptr, vt16, nullptr, nullptr, ctx16,
                                         S, HD, S, S, S, D,
                                         (long long)S * S, (long long)HD * S, (long long)HD, H, 1.f, 0, 2);

    // ---- 11) out = ctx @ wo (fp16 single) ----
    launch_gemm<128, 1, 1, false, 64, 2>(ctx16, nullptr, wot16, nullptr, outO, nullptr,
                                         S, D, D, D, D, D, 0, 0, 0, 1, 1.f, 0, 0);
}